// round 1
// baseline (speedup 1.0000x reference)
#include <cuda_runtime.h>
#include <stdint.h>

#define IN_F   2048
#define OUT_F  2048
#define TOPK   1024

// Scratch: masked weight, transposed to [k][n] for coalesced GEMM B loads.
__device__ float g_wt[(size_t)IN_F * OUT_F];

// ---------------------------------------------------------------------------
// Kernel 1: per-output-row exact top-k mask (radix select on |w| bit pattern,
// ties broken by lowest column index, matching jax.lax.top_k), then write the
// masked weight TRANSPOSED into g_wt[k][n].
// One block (256 threads) per output row.
// ---------------------------------------------------------------------------
__global__ void mask_transpose_kernel(const float* __restrict__ W) {
    __shared__ unsigned s_bits[IN_F];     // |w| bit patterns for this row
    __shared__ int      s_hist[256];
    __shared__ int      s_sel[2];
    __shared__ int      s_scan[257];

    const int row = blockIdx.x;
    const int tid = threadIdx.x;
    const float* wrow = W + (size_t)row * IN_F;

    for (int i = tid; i < IN_F; i += 256)
        s_bits[i] = __float_as_uint(wrow[i]) & 0x7fffffffu;
    __syncthreads();

    // MSB-first radix select: find exact bit pattern t of the k-th largest |w|.
    unsigned prefix = 0;
    int k = TOPK;
    #pragma unroll
    for (int pass = 0; pass < 4; ++pass) {
        const int shift = 24 - 8 * pass;
        s_hist[tid] = 0;
        __syncthreads();
        const unsigned pm = (pass == 0) ? 0u : (0xffffffffu << (shift + 8));
        for (int i = tid; i < IN_F; i += 256) {
            unsigned b = s_bits[i];
            if ((b & pm) == prefix)
                atomicAdd(&s_hist[(b >> shift) & 0xffu], 1);
        }
        __syncthreads();
        if (tid == 0) {
            int acc = 0, d = 255;
            for (; d > 0; --d) {
                int c = s_hist[d];
                if (acc + c >= k) break;
                acc += c;
            }
            s_sel[0] = d;
            s_sel[1] = k - acc;   // how many elements inside bin d we still need
        }
        __syncthreads();
        prefix |= ((unsigned)s_sel[0]) << shift;
        k = s_sel[1];
        __syncthreads();
    }
    const unsigned t = prefix;   // exact k-th largest |w| bit pattern
    const int kfin = k;          // # of ==t elements to keep (lowest index first)

    // Exclusive prefix over per-thread-chunk equality counts (blocked layout
    // keeps column-index order so tie-break matches the reference).
    const int CH = IN_F / 256;   // 8 contiguous columns per thread
    const int base = tid * CH;
    int cnt = 0;
    #pragma unroll
    for (int j = 0; j < CH; ++j)
        if (s_bits[base + j] == t) cnt++;
    s_scan[tid + 1] = cnt;
    if (tid == 0) s_scan[0] = 0;
    __syncthreads();
    if (tid == 0) {
        for (int i = 1; i <= 256; ++i) s_scan[i] += s_scan[i - 1];
    }
    __syncthreads();

    int eq_before = s_scan[tid];
    #pragma unroll
    for (int j = 0; j < CH; ++j) {
        const int c = base + j;
        const unsigned b = s_bits[c];
        float v = 0.0f;
        if (b > t) {
            v = wrow[c];
        } else if (b == t) {
            if (eq_before < kfin) v = wrow[c];
            eq_before++;
        }
        g_wt[(size_t)c * OUT_F + row] = v;   // transposed write
    }
}

// ---------------------------------------------------------------------------
// Kernel 2: SGEMM  C[m][n] = sum_k A[m][k] * Wt[k][n] + bias[n]
// A = x   [M x 2048] row-major
// Wt      [2048 x 2048] row-major (k-major) — from kernel 1
// 128x128 block tile, BK=16, 256 threads, 8x8 per-thread micro-tile.
// ---------------------------------------------------------------------------
#define BM 128
#define BN 128
#define BK 16
#define TM 8
#define TN 8

__global__ __launch_bounds__(256, 2)
void sgemm_kernel(const float* __restrict__ A,
                  const float* __restrict__ bias,
                  float* __restrict__ C) {
    __shared__ float As[BK][BM + 4];   // row stride 132 floats = 528B (16B mult.)
    __shared__ float Bs[BK][BN + 4];

    const int tid = threadIdx.x;
    const int tx = tid & 15;           // n direction
    const int ty = tid >> 4;           // m direction
    const int n0 = blockIdx.x * BN;
    const int m0 = blockIdx.y * BM;

    float acc[TM][TN] = {};

    for (int k0 = 0; k0 < IN_F; k0 += BK) {
        // A tile: 128 rows x 16 k. Each thread: 2 float4 loads, stored k-major.
        #pragma unroll
        for (int i = 0; i < 2; ++i) {
            const int idx = tid * 2 + i;         // 0..511
            const int m   = idx >> 2;            // 0..127
            const int k4  = (idx & 3) * 4;       // 0,4,8,12
            float4 v = *(const float4*)(A + (size_t)(m0 + m) * IN_F + k0 + k4);
            As[k4 + 0][m] = v.x;
            As[k4 + 1][m] = v.y;
            As[k4 + 2][m] = v.z;
            As[k4 + 3][m] = v.w;
        }
        // B tile: 16 k rows x 128 n, fully coalesced from g_wt.
        #pragma unroll
        for (int i = 0; i < 2; ++i) {
            const int idx = tid * 2 + i;
            const int kk  = idx >> 5;            // 0..15
            const int n4  = (idx & 31) * 4;      // 0..124
            float4 v = *(const float4*)(g_wt + (size_t)(k0 + kk) * OUT_F + n0 + n4);
            *(float4*)&Bs[kk][n4] = v;
        }
        __syncthreads();

        #pragma unroll
        for (int kk = 0; kk < BK; ++kk) {
            float a[TM], b[TN];
            #pragma unroll
            for (int i = 0; i < TM; ++i) a[i] = As[kk][ty * TM + i];
            #pragma unroll
            for (int j = 0; j < TN; ++j) b[j] = Bs[kk][tx * TN + j];
            #pragma unroll
            for (int i = 0; i < TM; ++i)
                #pragma unroll
                for (int j = 0; j < TN; ++j)
                    acc[i][j] += a[i] * b[j];
        }
        __syncthreads();
    }

    // Epilogue: add bias, vectorized stores.
    #pragma unroll
    for (int i = 0; i < TM; ++i) {
        const int m = m0 + ty * TM + i;
        #pragma unroll
        for (int j = 0; j < TN; j += 4) {
            const int n = n0 + tx * TN + j;
            float4 o;
            o.x = acc[i][j + 0] + bias[n + 0];
            o.y = acc[i][j + 1] + bias[n + 1];
            o.z = acc[i][j + 2] + bias[n + 2];
            o.w = acc[i][j + 3] + bias[n + 3];
            *(float4*)(C + (size_t)m * OUT_F + n) = o;
        }
    }
}

// ---------------------------------------------------------------------------
extern "C" void kernel_launch(void* const* d_in, const int* in_sizes, int n_in,
                              void* d_out, int out_size) {
    const float* x    = (const float*)d_in[0];   // [M, 2048]
    const float* W    = (const float*)d_in[1];   // [2048, 2048]
    const float* bias = (const float*)d_in[2];   // [2048]
    float* out = (float*)d_out;

    const int M = in_sizes[0] / IN_F;            // 16384

    mask_transpose_kernel<<<OUT_F, 256>>>(W);
    dim3 grid(OUT_F / BN, M / BM);
    sgemm_kernel<<<grid, 256>>>(x, bias, out);
}

// round 2
// speedup vs baseline: 3.1688x; 3.1688x over previous
#include <cuda_runtime.h>
#include <stdint.h>

#define IN_F   2048
#define OUT_F  2048
#define TOPK   1024
#define M_FIX  16384

// Scratch: masked W^T (tf32-rounded) [k][n], and tf32-rounded activations.
__device__ float g_wt[(size_t)IN_F * OUT_F];
__device__ float g_a [(size_t)M_FIX * IN_F];

__device__ __forceinline__ float tf32_rna(float f) {
    unsigned r;
    asm("cvt.rna.tf32.f32 %0, %1;" : "=r"(r) : "f"(f));
    return __uint_as_float(r);
}

// ---------------------------------------------------------------------------
// Kernel 1: per-row exact top-k mask (radix select on |w| bits, ties kept
// lowest-index-first like jax.lax.top_k), write masked W transposed + rounded
// to tf32 into g_wt[k][n]. One 256-thread block per output row.
// ---------------------------------------------------------------------------
__global__ void mask_transpose_kernel(const float* __restrict__ W) {
    __shared__ unsigned s_bits[IN_F];
    __shared__ int s_hist[256];
    __shared__ int s_sel[2];
    __shared__ int s_scan[257];

    const int row = blockIdx.x;
    const int tid = threadIdx.x;
    const float* wrow = W + (size_t)row * IN_F;

    for (int i = tid; i < IN_F; i += 256)
        s_bits[i] = __float_as_uint(wrow[i]) & 0x7fffffffu;
    __syncthreads();

    unsigned prefix = 0;
    int k = TOPK;
    #pragma unroll
    for (int pass = 0; pass < 4; ++pass) {
        const int shift = 24 - 8 * pass;
        s_hist[tid] = 0;
        __syncthreads();
        const unsigned pm = (pass == 0) ? 0u : (0xffffffffu << (shift + 8));
        for (int i = tid; i < IN_F; i += 256) {
            unsigned b = s_bits[i];
            if ((b & pm) == prefix)
                atomicAdd(&s_hist[(b >> shift) & 0xffu], 1);
        }
        __syncthreads();
        if (tid == 0) {
            int acc = 0, d = 255;
            for (; d > 0; --d) {
                int c = s_hist[d];
                if (acc + c >= k) break;
                acc += c;
            }
            s_sel[0] = d;
            s_sel[1] = k - acc;
        }
        __syncthreads();
        prefix |= ((unsigned)s_sel[0]) << shift;
        k = s_sel[1];
        __syncthreads();
    }
    const unsigned t = prefix;
    const int kfin = k;

    const int CH = IN_F / 256;
    const int base = tid * CH;
    int cnt = 0;
    #pragma unroll
    for (int j = 0; j < CH; ++j)
        if (s_bits[base + j] == t) cnt++;
    s_scan[tid + 1] = cnt;
    if (tid == 0) s_scan[0] = 0;
    __syncthreads();
    if (tid == 0)
        for (int i = 1; i <= 256; ++i) s_scan[i] += s_scan[i - 1];
    __syncthreads();

    int eq_before = s_scan[tid];
    #pragma unroll
    for (int j = 0; j < CH; ++j) {
        const int c = base + j;
        const unsigned b = s_bits[c];
        float v = 0.0f;
        if (b > t) {
            v = tf32_rna(wrow[c]);
        } else if (b == t) {
            if (eq_before < kfin) v = tf32_rna(wrow[c]);
            eq_before++;
        }
        g_wt[(size_t)c * OUT_F + row] = v;
    }
}

// ---------------------------------------------------------------------------
// Kernel 2: round activations to tf32 (RN) once.
// ---------------------------------------------------------------------------
__global__ void cvt_a_kernel(const float4* __restrict__ x, int n4) {
    int i = blockIdx.x * blockDim.x + threadIdx.x;
    if (i < n4) {
        float4 v = x[i];
        v.x = tf32_rna(v.x);
        v.y = tf32_rna(v.y);
        v.z = tf32_rna(v.z);
        v.w = tf32_rna(v.w);
        reinterpret_cast<float4*>(g_a)[i] = v;
    }
}

// ---------------------------------------------------------------------------
// Kernel 3: tf32 tensor-core GEMM. C[m][n] = sum_k A[m][k]*Wt[k][n] + bias[n]
// 128x128 block tile, BK=16, 256 threads, 2x4 warp grid (64x32 warp tiles),
// mma.sync.m16n8k8.tf32, cp.async double-buffered smem.
// ---------------------------------------------------------------------------
#define BM 128
#define BN 128
#define BK 16
#define AS_STRIDE 20    // ≡ 4 (mod 32): A-fragment LDS conflict-free
#define BS_STRIDE 136   // ≡ 8 (mod 32): B-fragment LDS conflict-free
#define NT (IN_F / BK)  // 128

__device__ __forceinline__ void cp8(unsigned dst, const void* src) {
    asm volatile("cp.async.ca.shared.global [%0], [%1], 8;\n" :: "r"(dst), "l"(src));
}
__device__ __forceinline__ void cp16(unsigned dst, const void* src) {
    asm volatile("cp.async.ca.shared.global [%0], [%1], 16;\n" :: "r"(dst), "l"(src));
}

__device__ __forceinline__ void mma_tf32(float c[4], const unsigned a[4], const unsigned b[2]) {
    asm volatile(
        "mma.sync.aligned.m16n8k8.row.col.f32.tf32.tf32.f32 "
        "{%0,%1,%2,%3}, {%4,%5,%6,%7}, {%8,%9}, {%0,%1,%2,%3};\n"
        : "+f"(c[0]), "+f"(c[1]), "+f"(c[2]), "+f"(c[3])
        : "r"(a[0]), "r"(a[1]), "r"(a[2]), "r"(a[3]), "r"(b[0]), "r"(b[1]));
}

__global__ __launch_bounds__(256, 2)
void tf32_gemm_kernel(const float* __restrict__ bias, float* __restrict__ C) {
    __shared__ float As[2][BM * AS_STRIDE];
    __shared__ float Bs[2][BK * BS_STRIDE];

    const int tid  = threadIdx.x;
    const int lane = tid & 31;
    const int wid  = tid >> 5;
    const int wm   = wid >> 2;   // 0..1
    const int wn   = wid & 3;    // 0..3
    const int g    = lane >> 2;  // 0..7
    const int t    = lane & 3;   // 0..3

    const int n0 = blockIdx.x * BN;
    const int m0 = blockIdx.y * BM;

    const unsigned as_base = (unsigned)__cvta_generic_to_shared(&As[0][0]);
    const unsigned bs_base = (unsigned)__cvta_generic_to_shared(&Bs[0][0]);
    const unsigned AS_BUF = BM * AS_STRIDE * 4;
    const unsigned BS_BUF = BK * BS_STRIDE * 4;

    float acc[4][4][4];
    #pragma unroll
    for (int i = 0; i < 4; ++i)
        #pragma unroll
        for (int j = 0; j < 4; ++j)
            #pragma unroll
            for (int q = 0; q < 4; ++q) acc[i][j][q] = 0.0f;

    auto issue_tile = [&](int kt, int buf) {
        const int k0 = kt * BK;
        // A tile: 128 rows x 16 k, float2 granules.
        #pragma unroll
        for (int r = 0; r < 4; ++r) {
            int lin = r * 256 + tid;
            int m = lin >> 3, j = lin & 7;
            const float* src = g_a + (size_t)(m0 + m) * IN_F + k0 + 2 * j;
            cp8(as_base + buf * AS_BUF + (m * AS_STRIDE + 2 * j) * 4, src);
        }
        // B tile: 16 k rows x 128 n, float4 granules (coalesced from g_wt).
        #pragma unroll
        for (int r = 0; r < 2; ++r) {
            int lin = r * 256 + tid;
            int k = lin >> 5, j = lin & 31;
            const float* src = g_wt + (size_t)(k0 + k) * OUT_F + n0 + 4 * j;
            cp16(bs_base + buf * BS_BUF + (k * BS_STRIDE + 4 * j) * 4, src);
        }
        asm volatile("cp.async.commit_group;\n" ::);
    };

    issue_tile(0, 0);

    for (int kt = 0; kt < NT; ++kt) {
        const int buf = kt & 1;
        if (kt + 1 < NT) {
            issue_tile(kt + 1, buf ^ 1);
            asm volatile("cp.async.wait_group 1;\n" ::);
        } else {
            asm volatile("cp.async.wait_group 0;\n" ::);
        }
        __syncthreads();

        const float* As_ = &As[buf][0];
        const float* Bs_ = &Bs[buf][0];

        #pragma unroll
        for (int kk = 0; kk < 2; ++kk) {
            unsigned a[4][4], b[4][2];
            #pragma unroll
            for (int mt = 0; mt < 4; ++mt) {
                const int row = wm * 64 + mt * 16 + g;
                const int kb  = kk * 8 + t;
                a[mt][0] = __float_as_uint(As_[row * AS_STRIDE + kb]);
                a[mt][1] = __float_as_uint(As_[(row + 8) * AS_STRIDE + kb]);
                a[mt][2] = __float_as_uint(As_[row * AS_STRIDE + kb + 4]);
                a[mt][3] = __float_as_uint(As_[(row + 8) * AS_STRIDE + kb + 4]);
            }
            #pragma unroll
            for (int nt = 0; nt < 4; ++nt) {
                const int col = wn * 32 + nt * 8 + g;
                b[nt][0] = __float_as_uint(Bs_[(kk * 8 + t) * BS_STRIDE + col]);
                b[nt][1] = __float_as_uint(Bs_[(kk * 8 + t + 4) * BS_STRIDE + col]);
            }
            #pragma unroll
            for (int mt = 0; mt < 4; ++mt)
                #pragma unroll
                for (int nt = 0; nt < 4; ++nt)
                    mma_tf32(acc[mt][nt], a[mt], b[nt]);
        }
        __syncthreads();
    }

    // Epilogue: bias add, float2 stores.
    #pragma unroll
    for (int mt = 0; mt < 4; ++mt) {
        const int r0 = m0 + wm * 64 + mt * 16 + g;
        #pragma unroll
        for (int nt = 0; nt < 4; ++nt) {
            const int cb = n0 + wn * 32 + nt * 8 + t * 2;
            const float2 bv = *reinterpret_cast<const float2*>(bias + cb);
            float2 o0, o1;
            o0.x = acc[mt][nt][0] + bv.x;
            o0.y = acc[mt][nt][1] + bv.y;
            o1.x = acc[mt][nt][2] + bv.x;
            o1.y = acc[mt][nt][3] + bv.y;
            *reinterpret_cast<float2*>(C + (size_t)r0 * OUT_F + cb) = o0;
            *reinterpret_cast<float2*>(C + (size_t)(r0 + 8) * OUT_F + cb) = o1;
        }
    }
}

// ---------------------------------------------------------------------------
extern "C" void kernel_launch(void* const* d_in, const int* in_sizes, int n_in,
                              void* d_out, int out_size) {
    const float* x    = (const float*)d_in[0];   // [M, 2048]
    const float* W    = (const float*)d_in[1];   // [2048, 2048]
    const float* bias = (const float*)d_in[2];   // [2048]
    float* out = (float*)d_out;

    const int M = in_sizes[0] / IN_F;            // 16384

    mask_transpose_kernel<<<OUT_F, 256>>>(W);
    const int n4 = M * IN_F / 4;
    cvt_a_kernel<<<(n4 + 255) / 256, 256>>>((const float4*)x, n4);
    dim3 grid(OUT_F / BN, M / BM);
    tf32_gemm_kernel<<<grid, 256>>>(bias, out);
}

// round 4
// speedup vs baseline: 4.1904x; 1.3224x over previous
#include <cuda_runtime.h>
#include <stdint.h>

#define IN_F   2048
#define OUT_F  2048
#define TOPK   1024

#define BM 128
#define BN 128
#define BK 32
#define NSTAGES 3
#define NT (IN_F / BK)              // 64
#define STAGE_BYTES 32768           // A 16KB + B 16KB
#define B_OFF 16384
#define DSMEM (NSTAGES * STAGE_BYTES + 1024)

// Scratch: masked W, tf32-RNA-rounded, native [out][in] row-major layout.
__device__ float g_wm[(size_t)OUT_F * IN_F];

__device__ __forceinline__ float tf32_rna(float f) {
    unsigned r;
    asm("cvt.rna.tf32.f32 %0, %1;" : "=r"(r) : "f"(f));
    return __uint_as_float(r);
}
__device__ __forceinline__ uint32_t rna_u(uint32_t v) {
    uint32_t r;
    asm("cvt.rna.tf32.f32 %0, %1;" : "=r"(r) : "f"(__uint_as_float(v)));
    return r;
}
__device__ __forceinline__ uint32_t smem_u32(const void* p) {
    return (uint32_t)__cvta_generic_to_shared(p);
}
__device__ __forceinline__ void cp16cg(uint32_t dst, const void* src) {
    asm volatile("cp.async.cg.shared.global [%0], [%1], 16;\n" :: "r"(dst), "l"(src));
}
__device__ __forceinline__ void ldm_x4(uint32_t (&r)[4], uint32_t addr) {
    asm volatile("ldmatrix.sync.aligned.m8n8.x4.shared.b16 {%0,%1,%2,%3}, [%4];"
                 : "=r"(r[0]), "=r"(r[1]), "=r"(r[2]), "=r"(r[3]) : "r"(addr));
}
__device__ __forceinline__ void mma_tf32(float c[4], const uint32_t a[4], const uint32_t b[2]) {
    asm volatile(
        "mma.sync.aligned.m16n8k8.row.col.f32.tf32.tf32.f32 "
        "{%0,%1,%2,%3}, {%4,%5,%6,%7}, {%8,%9}, {%0,%1,%2,%3};\n"
        : "+f"(c[0]), "+f"(c[1]), "+f"(c[2]), "+f"(c[3])
        : "r"(a[0]), "r"(a[1]), "r"(a[2]), "r"(a[3]), "r"(b[0]), "r"(b[1]));
}

// ---------------------------------------------------------------------------
// Kernel 1: per-row exact top-k mask (radix select on |w| bits, ties kept
// lowest-index-first per jax.lax.top_k). Parallel suffix/prefix scans.
// Writes masked W row-major, tf32-RNA rounded, into g_wm.
// ---------------------------------------------------------------------------
__global__ void mask_kernel(const float* __restrict__ W) {
    __shared__ unsigned s_bits[IN_F];
    __shared__ int s_hist[256];
    __shared__ int s_tmp[256];
    __shared__ int s_sel[2];

    const int row = blockIdx.x;
    const int tid = threadIdx.x;
    const float* wrow = W + (size_t)row * IN_F;

    for (int i = tid; i < IN_F; i += 256)
        s_bits[i] = __float_as_uint(wrow[i]) & 0x7fffffffu;
    __syncthreads();

    unsigned prefix = 0;
    int k = TOPK;
    #pragma unroll
    for (int pass = 0; pass < 4; ++pass) {
        const int shift = 24 - 8 * pass;
        s_hist[tid] = 0;
        __syncthreads();
        const unsigned pm = (pass == 0) ? 0u : (0xffffffffu << (shift + 8));
        for (int i = tid; i < IN_F; i += 256) {
            unsigned b = s_bits[i];
            if ((b & pm) == prefix)
                atomicAdd(&s_hist[(b >> shift) & 0xffu], 1);
        }
        __syncthreads();
        // Parallel inclusive SUFFIX scan of s_hist.
        int v = s_hist[tid];
        #pragma unroll
        for (int off = 1; off < 256; off <<= 1) {
            s_tmp[tid] = v;
            __syncthreads();
            if (tid + off < 256) v += s_tmp[tid + off];
            __syncthreads();
        }
        s_tmp[tid] = v;                 // s_tmp[d] = count of bins >= d
        __syncthreads();
        const int suf1 = (tid < 255) ? s_tmp[tid + 1] : 0;
        if (v >= k && suf1 < k) {       // exactly one d satisfies this
            s_sel[0] = tid;
            s_sel[1] = k - suf1;
        }
        __syncthreads();
        prefix |= ((unsigned)s_sel[0]) << shift;
        k = s_sel[1];
        __syncthreads();
    }
    const unsigned t = prefix;          // k-th largest |w| bit pattern
    const int kfin = k;                 // # of ==t to keep (lowest index first)

    // Count ==t per contiguous 8-col chunk, parallel inclusive prefix scan.
    const int CH = IN_F / 256;
    const int base = tid * CH;
    int cnt = 0;
    #pragma unroll
    for (int j = 0; j < CH; ++j)
        if (s_bits[base + j] == t) cnt++;
    int v2 = cnt;
    #pragma unroll
    for (int off = 1; off < 256; off <<= 1) {
        s_tmp[tid] = v2;
        __syncthreads();
        if (tid >= off) v2 += s_tmp[tid - off];
        __syncthreads();
    }
    int eq_before = v2 - cnt;           // exclusive prefix

    #pragma unroll
    for (int j = 0; j < CH; ++j) {
        const int c = base + j;
        const unsigned b = s_bits[c];
        float v = 0.0f;
        if (b > t) {
            v = tf32_rna(wrow[c]);
        } else if (b == t) {
            if (eq_before < kfin) v = tf32_rna(wrow[c]);
            eq_before++;
        }
        g_wm[(size_t)row * IN_F + c] = v;
    }
}

// ---------------------------------------------------------------------------
// Kernel 2: tf32 mma.sync GEMM.  C[m][n] = sum_k x[m][k]*Wm[n][k] + bias[n]
// 128x128 tile, BK=32, 128 threads, 2x2 warp grid, 64x64 warp tiles,
// ldmatrix.x4 fragments from XOR-swizzled smem, 3-stage cp.async ring,
// one __syncthreads per k-iter. A rounded to tf32 (RNA) in registers.
// ---------------------------------------------------------------------------
__global__ __launch_bounds__(128, 2)
void gemm_kernel(const float* __restrict__ x, const float* __restrict__ bias,
                 float* __restrict__ C) {
    extern __shared__ char dsm[];
    __shared__ float s_bias[BN];

    const int tid  = threadIdx.x;
    const int lane = tid & 31;
    const int wid  = tid >> 5;
    const int wm   = wid >> 1;           // 0..1
    const int wn   = wid & 1;            // 0..1
    const int m0 = blockIdx.y * BM;
    const int n0 = blockIdx.x * BN;

    const uint32_t base = (smem_u32(dsm) + 1023) & ~1023u;
    s_bias[tid] = bias[n0 + tid];

    // ldmatrix per-lane addressing: row-in-16 = lane&15, chunk-sel = lane>>4,
    // swizzle xor = (lane&7)<<4 (row-tile bases are multiples of 8).
    const int lrow = lane & 15;
    const int lsel = lane >> 4;
    const uint32_t lxor = (uint32_t)((lane & 7) << 4);

    auto issue = [&](int kt, int st) {
        const uint32_t sa = base + st * STAGE_BYTES;
        const int k0 = kt * BK;
        #pragma unroll
        for (int i = 0; i < 8; ++i) {            // A: 128 rows x 128B
            const int id = i * 128 + tid;
            const int m = id >> 3, j = id & 7;
            cp16cg(sa + m * 128 + (((uint32_t)(j << 4)) ^ ((uint32_t)((m & 7) << 4))),
                   x + (size_t)(m0 + m) * IN_F + k0 + j * 4);
        }
        #pragma unroll
        for (int i = 0; i < 8; ++i) {            // B: 128 rows x 128B
            const int id = i * 128 + tid;
            const int n = id >> 3, j = id & 7;
            cp16cg(sa + B_OFF + n * 128 + (((uint32_t)(j << 4)) ^ ((uint32_t)((n & 7) << 4))),
                   g_wm + (size_t)(n0 + n) * IN_F + k0 + j * 4);
        }
        asm volatile("cp.async.commit_group;\n" ::);
    };

    float acc[4][8][4] = {};

    issue(0, 0);
    issue(1, 1);

    int st = 0;
    for (int kt = 0; kt < NT; ++kt) {
        if (kt < NT - 2)
            asm volatile("cp.async.wait_group 1;\n" ::);
        else
            asm volatile("cp.async.wait_group 0;\n" ::);
        __syncthreads();

        if (kt + 2 < NT) {
            int st2 = st + 2;
            if (st2 >= NSTAGES) st2 -= NSTAGES;
            issue(kt + 2, st2);
        }

        const uint32_t sa = base + st * STAGE_BYTES;
        const uint32_t sb = sa + B_OFF;

        #pragma unroll
        for (int kk = 0; kk < 4; ++kk) {         // 4 k-chunks of 8 in BK=32
            const uint32_t csel = (((uint32_t)((kk * 2 + lsel) << 4)) ^ lxor);
            uint32_t a[4][4];
            uint32_t b[8][2];
            #pragma unroll
            for (int mt = 0; mt < 4; ++mt)
                ldm_x4(a[mt], sa + (uint32_t)((wm * 64 + mt * 16 + lrow) * 128) + csel);
            #pragma unroll
            for (int np = 0; np < 4; ++np) {
                uint32_t r[4];
                ldm_x4(r, sb + (uint32_t)((wn * 64 + np * 16 + lrow) * 128) + csel);
                b[2 * np][0] = r[0]; b[2 * np + 1][0] = r[1];
                b[2 * np][1] = r[2]; b[2 * np + 1][1] = r[3];
            }
            #pragma unroll
            for (int mt = 0; mt < 4; ++mt) {     // round A to tf32 (RNA)
                #pragma unroll
                for (int q = 0; q < 4; ++q) a[mt][q] = rna_u(a[mt][q]);
            }
            #pragma unroll
            for (int mt = 0; mt < 4; ++mt)
                #pragma unroll
                for (int nt = 0; nt < 8; ++nt)
                    mma_tf32(acc[mt][nt], a[mt], b[nt]);
        }
        ++st;
        if (st == NSTAGES) st = 0;
    }

    // Epilogue: bias add, float2 stores.
    const int g = lane >> 2;
    const int t = lane & 3;
    #pragma unroll
    for (int mt = 0; mt < 4; ++mt) {
        const int r0 = m0 + wm * 64 + mt * 16 + g;
        #pragma unroll
        for (int nt = 0; nt < 8; ++nt) {
            const int cl = wn * 64 + nt * 8 + t * 2;   // local col in [0,128)
            const float bx = s_bias[cl], by = s_bias[cl + 1];
            float2 o0, o1;
            o0.x = acc[mt][nt][0] + bx;
            o0.y = acc[mt][nt][1] + by;
            o1.x = acc[mt][nt][2] + bx;
            o1.y = acc[mt][nt][3] + by;
            *reinterpret_cast<float2*>(C + (size_t)r0 * OUT_F + n0 + cl) = o0;
            *reinterpret_cast<float2*>(C + (size_t)(r0 + 8) * OUT_F + n0 + cl) = o1;
        }
    }
}

// ---------------------------------------------------------------------------
extern "C" void kernel_launch(void* const* d_in, const int* in_sizes, int n_in,
                              void* d_out, int out_size) {
    const float* x    = (const float*)d_in[0];   // [M, 2048]
    const float* W    = (const float*)d_in[1];   // [2048, 2048]
    const float* bias = (const float*)d_in[2];   // [2048]
    float* out = (float*)d_out;

    const int M = in_sizes[0] / IN_F;            // 16384

    cudaFuncSetAttribute(gemm_kernel,
                         cudaFuncAttributeMaxDynamicSharedMemorySize, DSMEM);

    mask_kernel<<<OUT_F, 256>>>(W);
    dim3 grid(OUT_F / BN, M / BM);               // (16, 128)
    gemm_kernel<<<grid, 128, DSMEM>>>(x, bias, out);
}